// round 3
// baseline (speedup 1.0000x reference)
#include <cuda_runtime.h>
#include <cuda_bf16.h>
#include <math.h>

// MoE gate: logits = hs @ W^T  (N x 4), softmax over 4, top-2.
// Output layout (float):
//   [0, 2N)   : topk_idx  (as float)
//   [2N, 4N)  : topk_weight
//   [4N, 6N)  : row_idx   (row_idx[i][j] = j*N + i, as float)

constexpr int EMBED = 2560;
constexpr int NEXP  = 4;
constexpr int VEC   = EMBED / 4;   // 640 float4 per row
constexpr int WARPS_PER_BLOCK = 8; // 256 threads
constexpr int TOK_PER_WARP    = 4;
constexpr int TOK_PER_BLOCK   = WARPS_PER_BLOCK * TOK_PER_WARP;  // 32

#define FMA4(accv, h, wv)                                                     \
    accv = fmaf((h).x, (wv).x,                                                \
           fmaf((h).y, (wv).y,                                                \
           fmaf((h).z, (wv).z,                                                \
           fmaf((h).w, (wv).w, accv))))

__global__ __launch_bounds__(WARPS_PER_BLOCK * 32)
void moe_gate_kernel(const float* __restrict__ hs,
                     const float* __restrict__ w,
                     float* __restrict__ out,
                     int n) {
    const int lane = threadIdx.x & 31;
    const int wid  = threadIdx.x >> 5;
    const int tok0 = (blockIdx.x * WARPS_PER_BLOCK + wid) * TOK_PER_WARP;
    if (tok0 >= n) return;

    const float4* __restrict__ W4 = reinterpret_cast<const float4*>(w);
    const float4* __restrict__ H4 =
        reinterpret_cast<const float4*>(hs) + (size_t)tok0 * VEC;

    float acc[TOK_PER_WARP][NEXP];
#pragma unroll
    for (int i = 0; i < TOK_PER_WARP; i++)
#pragma unroll
        for (int e = 0; e < NEXP; e++) acc[i][e] = 0.0f;

    // Ping-pong prefetch: buffer A holds chunk c, buffer B chunk c+32.
    // While FMAs consume one buffer, the other buffer's loads are in flight.
    float4 ha[TOK_PER_WARP], hb[TOK_PER_WARP];
#pragma unroll
    for (int i = 0; i < TOK_PER_WARP; i++)
        ha[i] = H4[(size_t)i * VEC + lane];

    // 20 chunks per lane total; 10 iterations of 2 chunks.
    for (int c = lane; c < VEC; c += 64) {
        const int c2 = c + 32;          // always < VEC (max 639)
        const int c3 = c + 64;          // prefetch for next iter (predicated)

        // Issue B-buffer loads before computing on A.
#pragma unroll
        for (int i = 0; i < TOK_PER_WARP; i++)
            hb[i] = H4[(size_t)i * VEC + c2];

        {
            const float4 w0 = __ldg(&W4[0 * VEC + c]);
            const float4 w1 = __ldg(&W4[1 * VEC + c]);
            const float4 w2 = __ldg(&W4[2 * VEC + c]);
            const float4 w3 = __ldg(&W4[3 * VEC + c]);
#pragma unroll
            for (int i = 0; i < TOK_PER_WARP; i++) {
                FMA4(acc[i][0], ha[i], w0);
                FMA4(acc[i][1], ha[i], w1);
                FMA4(acc[i][2], ha[i], w2);
                FMA4(acc[i][3], ha[i], w3);
            }
        }

        // Prefetch next A (predicated off on the last iteration).
        if (c3 < VEC) {
#pragma unroll
            for (int i = 0; i < TOK_PER_WARP; i++)
                ha[i] = H4[(size_t)i * VEC + c3];
        }

        {
            const float4 w0 = __ldg(&W4[0 * VEC + c2]);
            const float4 w1 = __ldg(&W4[1 * VEC + c2]);
            const float4 w2 = __ldg(&W4[2 * VEC + c2]);
            const float4 w3 = __ldg(&W4[3 * VEC + c2]);
#pragma unroll
            for (int i = 0; i < TOK_PER_WARP; i++) {
                FMA4(acc[i][0], hb[i], w0);
                FMA4(acc[i][1], hb[i], w1);
                FMA4(acc[i][2], hb[i], w2);
                FMA4(acc[i][3], hb[i], w3);
            }
        }
    }

    // Full butterfly reduce: every lane ends with the complete sums.
#pragma unroll
    for (int i = 0; i < TOK_PER_WARP; i++)
#pragma unroll
        for (int e = 0; e < NEXP; e++) {
            float v = acc[i][e];
#pragma unroll
            for (int off = 16; off > 0; off >>= 1)
                v += __shfl_xor_sync(0xFFFFFFFFu, v, off);
            acc[i][e] = v;
        }

    if (lane < TOK_PER_WARP) {
        const int tok = tok0 + lane;
        if (tok < n) {
            float l[NEXP];
#pragma unroll
            for (int e = 0; e < NEXP; e++) l[e] = acc[lane][e];

            // softmax over 4
            float m = l[0];
#pragma unroll
            for (int e = 1; e < NEXP; e++) m = fmaxf(m, l[e]);
            float p[NEXP];
            float s = 0.0f;
#pragma unroll
            for (int e = 0; e < NEXP; e++) { p[e] = expf(l[e] - m); s += p[e]; }
            const float inv = 1.0f / s;
#pragma unroll
            for (int e = 0; e < NEXP; e++) p[e] *= inv;

            // top-2 with lowest-index tie-break (strict >)
            int bi = 0;
            float bv = p[0];
#pragma unroll
            for (int e = 1; e < NEXP; e++)
                if (p[e] > bv) { bv = p[e]; bi = e; }
            int si = -1;
            float sv = -1.0f;
#pragma unroll
            for (int e = 0; e < NEXP; e++) {
                if (e == bi) continue;
                if (p[e] > sv) { sv = p[e]; si = e; }
            }

            const size_t n2 = 2 * (size_t)n;
            out[(size_t)tok * 2 + 0]          = (float)bi;
            out[(size_t)tok * 2 + 1]          = (float)si;
            out[n2 + (size_t)tok * 2 + 0]     = bv;
            out[n2 + (size_t)tok * 2 + 1]     = sv;
            out[2 * n2 + (size_t)tok * 2 + 0] = (float)tok;
            out[2 * n2 + (size_t)tok * 2 + 1] = (float)(n + tok);
        }
    }
}

extern "C" void kernel_launch(void* const* d_in, const int* in_sizes, int n_in,
                              void* d_out, int out_size) {
    const float* hs = (const float*)d_in[0];
    const float* w  = (const float*)d_in[1];
    float* out      = (float*)d_out;

    const int n = in_sizes[0] / EMBED;  // 32768
    const int blocks = (n + TOK_PER_BLOCK - 1) / TOK_PER_BLOCK;
    moe_gate_kernel<<<blocks, WARPS_PER_BLOCK * 32>>>(hs, w, out, n);
}

// round 4
// speedup vs baseline: 1.1666x; 1.1666x over previous
#include <cuda_runtime.h>
#include <cuda_bf16.h>
#include <math.h>

// MoE gate: logits = hs @ W^T  (N x 4), softmax over 4, top-2.
// Output layout (float):
//   [0, 2N)   : topk_idx  (as float)
//   [2N, 4N)  : topk_weight
//   [4N, 6N)  : row_idx   (row_idx[i][j] = j*N + i, as float)

constexpr int EMBED = 2560;
constexpr int NEXP  = 4;
constexpr int VEC   = EMBED / 4;   // 640 float4 per row
constexpr int WARPS_PER_BLOCK = 8; // 256 threads
constexpr int TOK_PER_WARP    = 4;
constexpr int TOK_PER_BLOCK   = WARPS_PER_BLOCK * TOK_PER_WARP;  // 32

__device__ unsigned int g_strip_counter;

__global__ void reset_counter_kernel() { g_strip_counter = 0u; }

__global__ __launch_bounds__(WARPS_PER_BLOCK * 32)
void moe_gate_kernel(const float* __restrict__ hs,
                     const float* __restrict__ w,
                     float* __restrict__ out,
                     int n, int n_strips) {
    const int lane = threadIdx.x & 31;
    const int wid  = threadIdx.x >> 5;
    const float4* __restrict__ W4 = reinterpret_cast<const float4*>(w);

    __shared__ int s_strip;

    for (;;) {
        __syncthreads();                     // protect s_strip from previous read
        if (threadIdx.x == 0)
            s_strip = (int)atomicAdd(&g_strip_counter, 1u);
        __syncthreads();
        const int strip = s_strip;
        if (strip >= n_strips) return;

        const int tok0 = strip * TOK_PER_BLOCK + wid * TOK_PER_WARP;
        if (tok0 >= n) continue;

        const float4* __restrict__ H4 =
            reinterpret_cast<const float4*>(hs) + (size_t)tok0 * VEC;

        float acc[TOK_PER_WARP][NEXP];
#pragma unroll
        for (int i = 0; i < TOK_PER_WARP; i++)
#pragma unroll
            for (int e = 0; e < NEXP; e++) acc[i][e] = 0.0f;

        // R1's proven inner loop: 8 LDG.128 per iteration, compiler-scheduled.
        for (int c = lane; c < VEC; c += 32) {
            const float4 w0 = W4[0 * VEC + c];
            const float4 w1 = W4[1 * VEC + c];
            const float4 w2 = W4[2 * VEC + c];
            const float4 w3 = W4[3 * VEC + c];
#pragma unroll
            for (int i = 0; i < TOK_PER_WARP; i++) {
                const float4 h = H4[(size_t)i * VEC + c];
                acc[i][0] = fmaf(h.x, w0.x, fmaf(h.y, w0.y, fmaf(h.z, w0.z, fmaf(h.w, w0.w, acc[i][0]))));
                acc[i][1] = fmaf(h.x, w1.x, fmaf(h.y, w1.y, fmaf(h.z, w1.z, fmaf(h.w, w1.w, acc[i][1]))));
                acc[i][2] = fmaf(h.x, w2.x, fmaf(h.y, w2.y, fmaf(h.z, w2.z, fmaf(h.w, w2.w, acc[i][2]))));
                acc[i][3] = fmaf(h.x, w3.x, fmaf(h.y, w3.y, fmaf(h.z, w3.z, fmaf(h.w, w3.w, acc[i][3]))));
            }
        }

        // Full butterfly reduce: every lane ends with the complete sums.
#pragma unroll
        for (int i = 0; i < TOK_PER_WARP; i++)
#pragma unroll
            for (int e = 0; e < NEXP; e++) {
                float v = acc[i][e];
#pragma unroll
                for (int off = 16; off > 0; off >>= 1)
                    v += __shfl_xor_sync(0xFFFFFFFFu, v, off);
                acc[i][e] = v;
            }

        if (lane < TOK_PER_WARP) {
            const int tok = tok0 + lane;
            if (tok < n) {
                float l[NEXP];
#pragma unroll
                for (int e = 0; e < NEXP; e++) l[e] = acc[lane][e];

                // softmax over 4
                float m = l[0];
#pragma unroll
                for (int e = 1; e < NEXP; e++) m = fmaxf(m, l[e]);
                float p[NEXP];
                float s = 0.0f;
#pragma unroll
                for (int e = 0; e < NEXP; e++) { p[e] = expf(l[e] - m); s += p[e]; }
                const float inv = 1.0f / s;
#pragma unroll
                for (int e = 0; e < NEXP; e++) p[e] *= inv;

                // top-2 with lowest-index tie-break (strict >)
                int bi = 0;
                float bv = p[0];
#pragma unroll
                for (int e = 1; e < NEXP; e++)
                    if (p[e] > bv) { bv = p[e]; bi = e; }
                int si = -1;
                float sv = -1.0f;
#pragma unroll
                for (int e = 0; e < NEXP; e++) {
                    if (e == bi) continue;
                    if (p[e] > sv) { sv = p[e]; si = e; }
                }

                const size_t n2 = 2 * (size_t)n;
                out[(size_t)tok * 2 + 0]          = (float)bi;
                out[(size_t)tok * 2 + 1]          = (float)si;
                out[n2 + (size_t)tok * 2 + 0]     = bv;
                out[n2 + (size_t)tok * 2 + 1]     = sv;
                out[2 * n2 + (size_t)tok * 2 + 0] = (float)tok;
                out[2 * n2 + (size_t)tok * 2 + 1] = (float)(n + tok);
            }
        }
    }
}

extern "C" void kernel_launch(void* const* d_in, const int* in_sizes, int n_in,
                              void* d_out, int out_size) {
    const float* hs = (const float*)d_in[0];
    const float* w  = (const float*)d_in[1];
    float* out      = (float*)d_out;

    const int n = in_sizes[0] / EMBED;  // 32768
    const int n_strips = (n + TOK_PER_BLOCK - 1) / TOK_PER_BLOCK;  // 1024

    // Persistent grid: 4 blocks per SM (4 × 256 threads fits 64K regs at ~64
    // regs/thread). Host query runs only at graph-capture time.
    int num_sms = 148;
    cudaDeviceGetAttribute(&num_sms, cudaDevAttrMultiProcessorCount, 0);
    int blocks = 4 * num_sms;
    if (blocks > n_strips) blocks = n_strips;

    reset_counter_kernel<<<1, 1>>>();
    moe_gate_kernel<<<blocks, WARPS_PER_BLOCK * 32>>>(hs, w, out, n, n_strips);
}

// round 5
// speedup vs baseline: 1.1985x; 1.0273x over previous
#include <cuda_runtime.h>
#include <cuda_bf16.h>
#include <math.h>

// MoE gate: logits = hs @ W^T  (N x 4), softmax over 4, top-2.
// Output layout (float):
//   [0, 2N)   : topk_idx  (as float)
//   [2N, 4N)  : topk_weight
//   [4N, 6N)  : row_idx   (row_idx[i][j] = j*N + i, as float)

constexpr int EMBED = 2560;
constexpr int NEXP  = 4;
constexpr int VEC   = EMBED / 4;   // 640 float4 per row
constexpr int WARPS_PER_BLOCK = 8; // 256 threads
constexpr int TOK_PER_WARP    = 8;
constexpr int TOK_PER_BLOCK   = WARPS_PER_BLOCK * TOK_PER_WARP;  // 64

__global__ __launch_bounds__(WARPS_PER_BLOCK * 32, 2)
void moe_gate_kernel(const float* __restrict__ hs,
                     const float* __restrict__ w,
                     float* __restrict__ out,
                     int n) {
    const int lane = threadIdx.x & 31;
    const int wid  = threadIdx.x >> 5;
    const int tok0 = (blockIdx.x * WARPS_PER_BLOCK + wid) * TOK_PER_WARP;
    if (tok0 >= n) return;

    const float4* __restrict__ W4 = reinterpret_cast<const float4*>(w);
    const float4* __restrict__ H4 =
        reinterpret_cast<const float4*>(hs) + (size_t)tok0 * VEC;

    float acc[TOK_PER_WARP][NEXP];
#pragma unroll
    for (int i = 0; i < TOK_PER_WARP; i++)
#pragma unroll
        for (int e = 0; e < NEXP; e++) acc[i][e] = 0.0f;

    // Compiler-scheduled batch of 12 LDG.128 per iteration:
    //   8 hidden loads (DRAM stream, evict-first via __ldcs)
    //   4 weight loads (L1-resident; protected from thrash by __ldcs above)
    // Each weight float4 feeds 32 FMAs (8 tokens x 4 components).
    for (int c = lane; c < VEC; c += 32) {
        const float4 w0 = W4[0 * VEC + c];
        const float4 w1 = W4[1 * VEC + c];
        const float4 w2 = W4[2 * VEC + c];
        const float4 w3 = W4[3 * VEC + c];
        float4 h[TOK_PER_WARP];
#pragma unroll
        for (int i = 0; i < TOK_PER_WARP; i++)
            h[i] = __ldcs(&H4[(size_t)i * VEC + c]);
#pragma unroll
        for (int i = 0; i < TOK_PER_WARP; i++) {
            acc[i][0] = fmaf(h[i].x, w0.x, fmaf(h[i].y, w0.y, fmaf(h[i].z, w0.z, fmaf(h[i].w, w0.w, acc[i][0]))));
            acc[i][1] = fmaf(h[i].x, w1.x, fmaf(h[i].y, w1.y, fmaf(h[i].z, w1.z, fmaf(h[i].w, w1.w, acc[i][1]))));
            acc[i][2] = fmaf(h[i].x, w2.x, fmaf(h[i].y, w2.y, fmaf(h[i].z, w2.z, fmaf(h[i].w, w2.w, acc[i][2]))));
            acc[i][3] = fmaf(h[i].x, w3.x, fmaf(h[i].y, w3.y, fmaf(h[i].z, w3.z, fmaf(h[i].w, w3.w, acc[i][3]))));
        }
    }

    // Full butterfly reduce: every lane ends with the complete sums.
#pragma unroll
    for (int i = 0; i < TOK_PER_WARP; i++)
#pragma unroll
        for (int e = 0; e < NEXP; e++) {
            float v = acc[i][e];
#pragma unroll
            for (int off = 16; off > 0; off >>= 1)
                v += __shfl_xor_sync(0xFFFFFFFFu, v, off);
            acc[i][e] = v;
        }

    if (lane < TOK_PER_WARP) {
        const int tok = tok0 + lane;
        if (tok < n) {
            float l[NEXP];
#pragma unroll
            for (int e = 0; e < NEXP; e++) l[e] = acc[lane][e];

            // softmax over 4
            float m = l[0];
#pragma unroll
            for (int e = 1; e < NEXP; e++) m = fmaxf(m, l[e]);
            float p[NEXP];
            float s = 0.0f;
#pragma unroll
            for (int e = 0; e < NEXP; e++) { p[e] = expf(l[e] - m); s += p[e]; }
            const float inv = 1.0f / s;
#pragma unroll
            for (int e = 0; e < NEXP; e++) p[e] *= inv;

            // top-2 with lowest-index tie-break (strict >)
            int bi = 0;
            float bv = p[0];
#pragma unroll
            for (int e = 1; e < NEXP; e++)
                if (p[e] > bv) { bv = p[e]; bi = e; }
            int si = -1;
            float sv = -1.0f;
#pragma unroll
            for (int e = 0; e < NEXP; e++) {
                if (e == bi) continue;
                if (p[e] > sv) { sv = p[e]; si = e; }
            }

            const size_t n2 = 2 * (size_t)n;
            out[(size_t)tok * 2 + 0]          = (float)bi;
            out[(size_t)tok * 2 + 1]          = (float)si;
            out[n2 + (size_t)tok * 2 + 0]     = bv;
            out[n2 + (size_t)tok * 2 + 1]     = sv;
            out[2 * n2 + (size_t)tok * 2 + 0] = (float)tok;
            out[2 * n2 + (size_t)tok * 2 + 1] = (float)(n + tok);
        }
    }
}

extern "C" void kernel_launch(void* const* d_in, const int* in_sizes, int n_in,
                              void* d_out, int out_size) {
    const float* hs = (const float*)d_in[0];
    const float* w  = (const float*)d_in[1];
    float* out      = (float*)d_out;

    const int n = in_sizes[0] / EMBED;  // 32768
    const int blocks = (n + TOK_PER_BLOCK - 1) / TOK_PER_BLOCK;  // 512
    moe_gate_kernel<<<blocks, WARPS_PER_BLOCK * 32>>>(hs, w, out, n);
}